// round 10
// baseline (speedup 1.0000x reference)
#include <cuda_runtime.h>
#include <cstdint>

// Binarization (braq high_order_residual, order=2), shape (11008, 4096).
// Inputs per metadata order: x (float32), mask (int32 — harness promotes bool).
//
// One CTA per row. 256 threads x 16 elems/thread = 4096. Per-element data is
// register-resident for the whole kernel: global memory touched exactly once
// for read (x, mask) and once for write (out). Streaming cache hints (.cs)
// everywhere — zero reuse workload.
//   pass A: cnt = sum(m), sum1 = sum(x*m)                -> mean1
//   pass B: sabs1 = sum|c1|, ssign1 = sum sign(c1)       -> scale1
//           c1 = (x - mean1)*m
//   mean2 folded algebraically:
//           sum(r2) = sum1 - scale1*ssign1 - mean1*cnt
//           (r2 = (x - b1)*m, b1 = sign(c1)*scale1 + mean1)
//   pass C: sabs2 = sum|c2|, c2 = (r2 - mean2)*m         -> scale2
//   out    = m * (b1 + b2),  b2 = sign(c2)*scale2 + mean2

#define IC       4096
#define THREADS  256
#define F4       4        // float4 chunks per thread (16 elements)

__device__ __forceinline__ float sgnf(float c) {
    // matches jnp.sign: sign(0) == 0
    return (c > 0.f) ? 1.f : ((c < 0.f) ? -1.f : 0.f);
}

__global__ void __launch_bounds__(THREADS, 1)
binarization_kernel(const float* __restrict__ x,
                    const int* __restrict__ mask,     // int32 0/1
                    float* __restrict__ out)
{
    const size_t row = blockIdx.x;
    const float4* __restrict__ x4 = reinterpret_cast<const float4*>(x    + row * IC);
    const int4*   __restrict__ m4 = reinterpret_cast<const int4*>(mask   + row * IC);
    float4*       __restrict__ o4 = reinterpret_cast<float4*>(out        + row * IC);

    const int tid  = threadIdx.x;
    const int lane = tid & 31;
    const int wid  = tid >> 5;

    // ---- load: front-batched 128-bit streaming LDGs (MLP=8) ----
    float v[16];          // masked x values (0 outside mask)
    unsigned mb = 0u;     // 16-bit mask word
    #pragma unroll
    for (int j = 0; j < F4; j++) {
        float4 xv = __ldcs(&x4[tid + THREADS * j]);
        int4   mv = __ldcs(&m4[tid + THREADS * j]);
        const int b = j * 4;
        v[b + 0] = mv.x ? xv.x : 0.f;  mb |= (mv.x ? 1u : 0u) << (b + 0);
        v[b + 1] = mv.y ? xv.y : 0.f;  mb |= (mv.y ? 1u : 0u) << (b + 1);
        v[b + 2] = mv.z ? xv.z : 0.f;  mb |= (mv.z ? 1u : 0u) << (b + 2);
        v[b + 3] = mv.w ? xv.w : 0.f;  mb |= (mv.w ? 1u : 0u) << (b + 3);
    }

    __shared__ float s0[8], s1[8];

    auto reduce2 = [&](float& a, float& b) {
        #pragma unroll
        for (int o = 16; o; o >>= 1) {
            a += __shfl_xor_sync(0xffffffffu, a, o);
            b += __shfl_xor_sync(0xffffffffu, b, o);
        }
        __syncthreads();                 // protect smem reuse from previous read phase
        if (lane == 0) { s0[wid] = a; s1[wid] = b; }
        __syncthreads();
        a = 0.f; b = 0.f;
        #pragma unroll
        for (int w = 0; w < 8; w++) { a += s0[w]; b += s1[w]; }
    };

    // ---- pass A: count + masked sum ----
    float cnt = 0.f, sum1 = 0.f;
    #pragma unroll
    for (int i = 0; i < 16; i++) {
        cnt  += ((mb >> i) & 1u) ? 1.f : 0.f;
        sum1 += v[i];
    }
    reduce2(cnt, sum1);
    const bool  has   = cnt > 0.f;
    const float inv   = 1.f / fmaxf(cnt, 1.f);
    const float mean1 = has ? sum1 * inv : 0.f;

    // ---- pass B: sum|c1| and sum sign(c1) ----
    float sabs1 = 0.f, ssign1 = 0.f;
    #pragma unroll
    for (int i = 0; i < 16; i++) {
        const float mfi = ((mb >> i) & 1u) ? 1.f : 0.f;
        const float c1  = (v[i] - mean1) * mfi;
        sabs1  += fabsf(c1);
        ssign1 += sgnf(c1);
    }
    reduce2(sabs1, ssign1);
    const float scale1 = has ? sabs1 * inv : 0.f;
    // mean of r2 = (x - b1)*m, with sum(b1 over mask) = scale1*ssign1 + mean1*cnt
    const float mean2  = has ? (sum1 - scale1 * ssign1 - mean1 * cnt) * inv : 0.f;

    // ---- pass C: sum|c2| ----
    float sabs2 = 0.f, dummy = 0.f;
    #pragma unroll
    for (int i = 0; i < 16; i++) {
        const float mfi = ((mb >> i) & 1u) ? 1.f : 0.f;
        const float c1  = (v[i] - mean1) * mfi;
        const float b1  = sgnf(c1) * scale1 + mean1;
        const float r2  = (v[i] - b1) * mfi;
        const float c2  = (r2 - mean2) * mfi;
        sabs2 += fabsf(c2);
    }
    reduce2(sabs2, dummy);
    const float scale2 = has ? sabs2 * inv : 0.f;

    // ---- final: compute and store (128-bit streaming STGs) ----
    #pragma unroll
    for (int j = 0; j < F4; j++) {
        float4 ov;
        float* po = &ov.x;
        #pragma unroll
        for (int k = 0; k < 4; k++) {
            const int   i   = j * 4 + k;
            const float mfi = ((mb >> i) & 1u) ? 1.f : 0.f;
            const float c1  = (v[i] - mean1) * mfi;
            const float b1  = sgnf(c1) * scale1 + mean1;
            const float r2  = (v[i] - b1) * mfi;
            const float c2  = (r2 - mean2) * mfi;
            const float b2  = sgnf(c2) * scale2 + mean2;
            po[k] = mfi * (b1 + b2);
        }
        __stcs(&o4[tid + THREADS * j], ov);
    }
}

extern "C" void kernel_launch(void* const* d_in, const int* in_sizes, int n_in,
                              void* d_out, int out_size)
{
    const float* x    = (const float*)d_in[0];
    const int*   mask = (const int*)d_in[1];
    float*       out  = (float*)d_out;

    const int rows = in_sizes[0] / IC;   // 11008
    binarization_kernel<<<rows, THREADS>>>(x, mask, out);
}